// round 7
// baseline (speedup 1.0000x reference)
#include <cuda_runtime.h>
#include <math.h>

#define BATCH  8
#define SEQ    1024
#define DMODEL 1024
#define HEADS  16
#define DHEAD  64
#define TOPK   32
#define BHTOT  (BATCH*HEADS)     // 128
#define NROWS  (BATCH*SEQ)       // 8192

// ---------------- scratch (device globals: allocation-free) ----------------
__device__ float g_q [(size_t)BHTOT*SEQ*DHEAD];   // [b,h,s,d]  32MB
__device__ float g_k [(size_t)BHTOT*SEQ*DHEAD];   // [b,h,s,d]  32MB (pre-transpose)
__device__ float g_kT[(size_t)BHTOT*DHEAD*SEQ];   // [b,h,d,s]  32MB
__device__ float g_v [(size_t)BHTOT*SEQ*DHEAD];   // [b,h,s,d]  32MB
__device__ float g_vsum[BHTOT*DHEAD];             // per-(b,h) column sum of v

// ---------------- Q/K projection GEMM (z = 0:Q 1:K), exact scalar fp32 ------
// C = X[8192,1024]*W[1024,1024]+b, register-double-buffered, scalar FFMA.
// Accumulation order bitwise identical to prior rounds.
__global__ __launch_bounds__(256, 2) void proj_kernel(
    const float* __restrict__ X0, const float* __restrict__ X1,
    const float* __restrict__ W0, const float* __restrict__ W1,
    const float* __restrict__ b0, const float* __restrict__ b1,
    float* __restrict__ o0, float* __restrict__ o1)
{
    const int BM = 128, BN = 128, BK = 16;
    __shared__ float As[2][BK][BM];
    __shared__ float Bs[2][BK][BN];

    const int z = blockIdx.z;
    const float* X    = (z == 0) ? X0 : X1;
    const float* W    = (z == 0) ? W0 : W1;
    const float* bias = (z == 0) ? b0 : b1;
    float*       out  = (z == 0) ? o0 : o1;

    const int row0 = blockIdx.x * BM;
    const int col0 = blockIdx.y * BN;
    const int t  = threadIdx.x;
    const int tx = t & 15, ty = t >> 4;

    const int ar0 = t >> 2, ar1 = (t >> 2) + 64;
    const int akg = (t & 3) * 4;
    const int bk0 = t >> 5, bk1 = (t >> 5) + 8;
    const int bcg = (t & 31) * 4;

    float acc[8][8];
#pragma unroll
    for (int i = 0; i < 8; i++)
#pragma unroll
        for (int j = 0; j < 8; j++) acc[i][j] = 0.f;

    float4 ra0, ra1, rb0, rb1;

    ra0 = *(const float4*)(X + (size_t)(row0 + ar0)*DMODEL + akg);
    ra1 = *(const float4*)(X + (size_t)(row0 + ar1)*DMODEL + akg);
    rb0 = *(const float4*)(W + (size_t)bk0*DMODEL + col0 + bcg);
    rb1 = *(const float4*)(W + (size_t)bk1*DMODEL + col0 + bcg);
    As[0][akg+0][ar0] = ra0.x; As[0][akg+1][ar0] = ra0.y;
    As[0][akg+2][ar0] = ra0.z; As[0][akg+3][ar0] = ra0.w;
    As[0][akg+0][ar1] = ra1.x; As[0][akg+1][ar1] = ra1.y;
    As[0][akg+2][ar1] = ra1.z; As[0][akg+3][ar1] = ra1.w;
    *(float4*)&Bs[0][bk0][bcg] = rb0;
    *(float4*)&Bs[0][bk1][bcg] = rb1;
    __syncthreads();

    int buf = 0;
    for (int k0 = 0; k0 < DMODEL; k0 += BK) {
        const bool has_next = (k0 + BK < DMODEL);
        if (has_next) {
            const int kn = k0 + BK;
            ra0 = *(const float4*)(X + (size_t)(row0 + ar0)*DMODEL + kn + akg);
            ra1 = *(const float4*)(X + (size_t)(row0 + ar1)*DMODEL + kn + akg);
            rb0 = *(const float4*)(W + (size_t)(kn + bk0)*DMODEL + col0 + bcg);
            rb1 = *(const float4*)(W + (size_t)(kn + bk1)*DMODEL + col0 + bcg);
        }

#pragma unroll
        for (int kk = 0; kk < BK; kk++) {
            float a[8], b[8];
            *(float4*)(a+0) = *(const float4*)&As[buf][kk][ty*8 + 0];
            *(float4*)(a+4) = *(const float4*)&As[buf][kk][ty*8 + 4];
            *(float4*)(b+0) = *(const float4*)&Bs[buf][kk][tx*8 + 0];
            *(float4*)(b+4) = *(const float4*)&Bs[buf][kk][tx*8 + 4];
#pragma unroll
            for (int i = 0; i < 8; i++)
#pragma unroll
                for (int j = 0; j < 8; j++)
                    acc[i][j] = fmaf(a[i], b[j], acc[i][j]);
        }

        if (has_next) {
            const int nb = buf ^ 1;
            As[nb][akg+0][ar0] = ra0.x; As[nb][akg+1][ar0] = ra0.y;
            As[nb][akg+2][ar0] = ra0.z; As[nb][akg+3][ar0] = ra0.w;
            As[nb][akg+0][ar1] = ra1.x; As[nb][akg+1][ar1] = ra1.y;
            As[nb][akg+2][ar1] = ra1.z; As[nb][akg+3][ar1] = ra1.w;
            *(float4*)&Bs[nb][bk0][bcg] = rb0;
            *(float4*)&Bs[nb][bk1][bcg] = rb1;
            __syncthreads();
            buf = nb;
        }
    }

#pragma unroll
    for (int i = 0; i < 8; i++) {
        int row = row0 + ty*8 + i;
        int b = row >> 10, s = row & (SEQ-1);
#pragma unroll
        for (int j = 0; j < 8; j++) {
            int col = col0 + tx*8 + j;
            float val = acc[i][j] + __ldg(bias + col);
            int h = col >> 6, d = col & 63;
            size_t bh = (size_t)b*HEADS + h;
            out[(bh*SEQ + s)*DHEAD + d] = val;
        }
    }
}

// ---------------- V projection via 3xTF32 tensor cores ----------------------
// v = X@Wv + bv with x = hi + lo (tf32 split): D += Ahi*Bhi + Ahi*Blo + Alo*Bhi
// Per-element error ~3e-7 — enters the output smoothly (precision-safe).
__device__ __forceinline__ unsigned to_tf32(float x) {
    unsigned r; asm("cvt.rna.tf32.f32 %0, %1;" : "=r"(r) : "f"(x)); return r;
}
__device__ __forceinline__ void mma_tf32(
    float& d0, float& d1, float& d2, float& d3,
    unsigned a0, unsigned a1, unsigned a2, unsigned a3,
    unsigned b0, unsigned b1)
{
    asm("mma.sync.aligned.m16n8k8.row.col.f32.tf32.tf32.f32 "
        "{%0,%1,%2,%3}, {%4,%5,%6,%7}, {%8,%9}, {%0,%1,%2,%3};"
        : "+f"(d0), "+f"(d1), "+f"(d2), "+f"(d3)
        : "r"(a0), "r"(a1), "r"(a2), "r"(a3), "r"(b0), "r"(b1));
}

#define VP_AS 132   // padded A stride (conflict-free fragment loads)
#define VP_BS 68    // padded B stride

__global__ __launch_bounds__(256) void vproj_kernel(
    const float* __restrict__ X, const float* __restrict__ W,
    const float* __restrict__ bias)
{
    // block tile: 128(M) x 64(N); 8 warps in 4(M) x 2(N); warp tile 32x32
    __shared__ unsigned Ahi[16][VP_AS], Alo[16][VP_AS];   // [k][m]
    __shared__ unsigned Bhi[16][VP_BS], Blo[16][VP_BS];   // [k][n]

    const int row0 = blockIdx.x * 128;
    const int col0 = blockIdx.y * 64;       // == head * 64
    const int t    = threadIdx.x;
    const int warp = t >> 5, lane = t & 31;
    const int wm = warp & 3, wn = warp >> 2;
    const int g  = lane >> 2, tg = lane & 3;    // groupID, thread-in-group

    float d[2][4][4];                        // [m16 tile][n8 tile][frag]
#pragma unroll
    for (int i = 0; i < 2; i++)
#pragma unroll
        for (int j = 0; j < 4; j++)
#pragma unroll
            for (int c = 0; c < 4; c++) d[i][j][c] = 0.f;

    // loader indices: A: thread -> row m = t>>1, 8 k at (t&1)*8
    const int am  = t >> 1;
    const int aks = (t & 1) * 8;
    // B: thread -> k = t>>4, 4 n at (t&15)*4
    const int bk  = t >> 4;
    const int bns = (t & 15) * 4;

    for (int k0 = 0; k0 < DMODEL; k0 += 16) {
        // load + split A tile 128x16
        {
            const float* src = X + (size_t)(row0 + am)*DMODEL + k0 + aks;
            float4 v0 = *(const float4*)(src);
            float4 v1 = *(const float4*)(src + 4);
            float xs[8] = {v0.x, v0.y, v0.z, v0.w, v1.x, v1.y, v1.z, v1.w};
#pragma unroll
            for (int i = 0; i < 8; i++) {
                unsigned hi = to_tf32(xs[i]);
                float lof = xs[i] - __uint_as_float(hi);
                Ahi[aks + i][am] = hi;
                Alo[aks + i][am] = to_tf32(lof);
            }
        }
        // load + split B tile 16x64
        {
            const float* src = W + (size_t)(k0 + bk)*DMODEL + col0 + bns;
            float4 v = *(const float4*)(src);
            float xs[4] = {v.x, v.y, v.z, v.w};
#pragma unroll
            for (int i = 0; i < 4; i++) {
                unsigned hi = to_tf32(xs[i]);
                float lof = xs[i] - __uint_as_float(hi);
                Bhi[bk][bns + i] = hi;
                Blo[bk][bns + i] = to_tf32(lof);
            }
        }
        __syncthreads();

#pragma unroll
        for (int ks = 0; ks < 2; ks++) {
            const int kb = ks * 8;
            // B fragments for all 4 n8 tiles
            unsigned bh_[4][2], bl_[4][2];
#pragma unroll
            for (int nt = 0; nt < 4; nt++) {
                const int n = wn*32 + nt*8 + g;
                bh_[nt][0] = Bhi[kb + tg][n];
                bh_[nt][1] = Bhi[kb + tg + 4][n];
                bl_[nt][0] = Blo[kb + tg][n];
                bl_[nt][1] = Blo[kb + tg + 4][n];
            }
#pragma unroll
            for (int mt = 0; mt < 2; mt++) {
                const int m = wm*32 + mt*16;
                // A fragment: a0(g,tg) a1(g+8,tg) a2(g,tg+4) a3(g+8,tg+4)
                unsigned ah0 = Ahi[kb + tg    ][m + g];
                unsigned ah1 = Ahi[kb + tg    ][m + g + 8];
                unsigned ah2 = Ahi[kb + tg + 4][m + g];
                unsigned ah3 = Ahi[kb + tg + 4][m + g + 8];
                unsigned al0 = Alo[kb + tg    ][m + g];
                unsigned al1 = Alo[kb + tg    ][m + g + 8];
                unsigned al2 = Alo[kb + tg + 4][m + g];
                unsigned al3 = Alo[kb + tg + 4][m + g + 8];
#pragma unroll
                for (int nt = 0; nt < 4; nt++) {
                    float* dd = d[mt][nt];
                    mma_tf32(dd[0], dd[1], dd[2], dd[3],
                             ah0, ah1, ah2, ah3, bh_[nt][0], bh_[nt][1]);
                    mma_tf32(dd[0], dd[1], dd[2], dd[3],
                             ah0, ah1, ah2, ah3, bl_[nt][0], bl_[nt][1]);
                    mma_tf32(dd[0], dd[1], dd[2], dd[3],
                             al0, al1, al2, al3, bh_[nt][0], bh_[nt][1]);
                }
            }
        }
        __syncthreads();
    }

    // epilogue: c0:(g,2tg) c1:(g,2tg+1) c2:(g+8,2tg) c3:(g+8,2tg+1)
    const int head = col0 >> 6;
#pragma unroll
    for (int mt = 0; mt < 2; mt++) {
#pragma unroll
        for (int nt = 0; nt < 4; nt++) {
            const int dcol = wn*32 + nt*8 + 2*tg;   // 0..63 within head
#pragma unroll
            for (int half = 0; half < 2; half++) {
                const int row = row0 + wm*32 + mt*16 + g + half*8;
                const int b = row >> 10, s = row & (SEQ-1);
                float* dst = g_v + (((size_t)b*HEADS + head)*SEQ + s)*DHEAD + dcol;
                float2 o;
                o.x = d[mt][nt][half*2 + 0] + __ldg(bias + head*64 + dcol);
                o.y = d[mt][nt][half*2 + 1] + __ldg(bias + head*64 + dcol + 1);
                *(float2*)dst = o;
            }
        }
    }
}

// ---------------- K transpose: g_k[bh][s][d] -> g_kT[bh][d][s] --------------
__global__ __launch_bounds__(256) void ktrans_kernel()
{
    __shared__ float tile[64][65];
    const int bh = blockIdx.x;
    const int s0 = blockIdx.y * 64;
    const int t  = threadIdx.x;
    {
        const int r  = t >> 2;
        const int dc = (t & 3) * 16;
        const float4* src =
            (const float4*)(g_k + ((size_t)bh*SEQ + s0 + r)*DHEAD + dc);
#pragma unroll
        for (int i = 0; i < 4; i++) {
            float4 v = src[i];
            tile[r][dc + i*4 + 0] = v.x;
            tile[r][dc + i*4 + 1] = v.y;
            tile[r][dc + i*4 + 2] = v.z;
            tile[r][dc + i*4 + 3] = v.w;
        }
    }
    __syncthreads();
    {
        const int dd = t >> 2;
        const int sc = (t & 3) * 16;
        float* dst = g_kT + ((size_t)bh*DHEAD + dd)*SEQ + s0 + sc;
#pragma unroll
        for (int i = 0; i < 4; i++) {
            float4 v;
            v.x = tile[sc + i*4 + 0][dd];
            v.y = tile[sc + i*4 + 1][dd];
            v.z = tile[sc + i*4 + 2][dd];
            v.w = tile[sc + i*4 + 3][dd];
            *(float4*)(dst + i*4) = v;
        }
    }
}

// ---------------- per-(b,h) v column sums (1024 threads) ----------------
__global__ __launch_bounds__(1024) void vsum_kernel()
{
    __shared__ float red[1024];
    const int bh = blockIdx.x;
    const int t = threadIdx.x;
    const int d = t & 63, c = t >> 6;
    float s = 0.f;
    for (int si = c; si < SEQ; si += 16)
        s += g_v[((size_t)bh*SEQ + si)*DHEAD + d];
    red[t] = s;
    __syncthreads();
    if (t < 512) red[t] += red[t + 512];
    __syncthreads();
    if (t < 256) red[t] += red[t + 256];
    __syncthreads();
    if (t < 128) red[t] += red[t + 128];
    __syncthreads();
    if (t < 64)
        g_vsum[bh*DHEAD + d] = red[t] + red[t + 64];
}

// ---------------- fused scores + top-k + context ----------------
#define TQ 16
#define LISTCAP 48
#define ATTN_SMEM_BYTES ((TQ*SEQ + DHEAD*TQ + TQ*LISTCAP + TQ*LISTCAP) * 4)
static_assert(ATTN_SMEM_BYTES < 227 * 1024, "smem over sm_100a limit");

__global__ __launch_bounds__(256, 2) void attn_kernel(float* __restrict__ out)
{
    extern __shared__ float smem[];
    float (*sc)[SEQ] = (float(*)[SEQ])smem;
    float (*qs)[TQ]  = (float(*)[TQ])(smem + TQ*SEQ);
    int*   ridx      = (int*)(smem + TQ*SEQ + DHEAD*TQ);
    float* rw        = (float*)(ridx + TQ*LISTCAP);

    const int bh = blockIdx.y;
    const int s0 = blockIdx.x * TQ;
    const int t  = threadIdx.x;

    {
        int r  = t >> 4;
        int kg = (t & 15) * 4;
        float4 v = *(const float4*)(g_q + ((size_t)bh*SEQ + s0 + r)*DHEAD + kg);
        qs[kg+0][r] = v.x; qs[kg+1][r] = v.y; qs[kg+2][r] = v.z; qs[kg+3][r] = v.w;
    }
    __syncthreads();

    {
        const float* kp = g_kT + (size_t)bh*DHEAD*SEQ + 4*t;
        float acc[TQ][4];
#pragma unroll
        for (int r = 0; r < TQ; r++)
#pragma unroll
            for (int j = 0; j < 4; j++) acc[r][j] = 0.f;

        float4 kv0 = *(const float4*)(kp);
        float4 kv1 = *(const float4*)(kp + SEQ);

#pragma unroll 2
        for (int kk = 0; kk < DHEAD; kk += 2) {
            float4 n0 = kv0, n1 = kv1;
            if (kk + 2 < DHEAD) {
                n0 = *(const float4*)(kp + (size_t)(kk+2)*SEQ);
                n1 = *(const float4*)(kp + (size_t)(kk+3)*SEQ);
            }
            {
                float qv[TQ];
                *(float4*)(qv+0)  = *(const float4*)&qs[kk][0];
                *(float4*)(qv+4)  = *(const float4*)&qs[kk][4];
                *(float4*)(qv+8)  = *(const float4*)&qs[kk][8];
                *(float4*)(qv+12) = *(const float4*)&qs[kk][12];
#pragma unroll
                for (int r = 0; r < TQ; r++) {
                    acc[r][0] = fmaf(qv[r], kv0.x, acc[r][0]);
                    acc[r][1] = fmaf(qv[r], kv0.y, acc[r][1]);
                    acc[r][2] = fmaf(qv[r], kv0.z, acc[r][2]);
                    acc[r][3] = fmaf(qv[r], kv0.w, acc[r][3]);
                }
            }
            {
                float qv[TQ];
                *(float4*)(qv+0)  = *(const float4*)&qs[kk+1][0];
                *(float4*)(qv+4)  = *(const float4*)&qs[kk+1][4];
                *(float4*)(qv+8)  = *(const float4*)&qs[kk+1][8];
                *(float4*)(qv+12) = *(const float4*)&qs[kk+1][12];
#pragma unroll
                for (int r = 0; r < TQ; r++) {
                    acc[r][0] = fmaf(qv[r], kv1.x, acc[r][0]);
                    acc[r][1] = fmaf(qv[r], kv1.y, acc[r][1]);
                    acc[r][2] = fmaf(qv[r], kv1.z, acc[r][2]);
                    acc[r][3] = fmaf(qv[r], kv1.w, acc[r][3]);
                }
            }
            kv0 = n0; kv1 = n1;
        }

        const float scale = 0.125f;
#pragma unroll
        for (int r = 0; r < TQ; r++) {
            float4 o;
            o.x = acc[r][0]*scale; o.y = acc[r][1]*scale;
            o.z = acc[r][2]*scale; o.w = acc[r][3]*scale;
            *(float4*)&sc[r][4*t] = o;
        }
    }
    __syncthreads();

    const int warp = t >> 5, lane = t & 31;
    const int b = bh >> 4, h = bh & 15;

    for (int rr = 0; rr < 2; rr++) {
        const int row = warp*2 + rr;

        unsigned key[32];
#pragma unroll
        for (int i = 0; i < 32; i++) {
            unsigned u = __float_as_uint(sc[row][i*32 + lane]);
            key[i] = (u & 0x80000000u) ? ~u : (u | 0x80000000u);
        }

        unsigned lo = 0u, hi = 0xFFFFFFFFu;
        int clo = SEQ;
        while (hi - lo > 1u) {
            unsigned m = lo + ((hi - lo) >> 1);
            int c = 0;
#pragma unroll
            for (int i = 0; i < 32; i++) c += (key[i] >= m);
            c = (int)__reduce_add_sync(0xFFFFFFFFu, (unsigned)c);   // REDUX.SUM
            if (c == TOPK) { lo = m; clo = c; break; }
            if (c >  TOPK) { lo = m; clo = c; }
            else           { hi = m; }
        }
        const unsigned thr = lo;
        const int cnt = clo;

        float esum = 0.f;
        int base = 0;
#pragma unroll 1
        for (int i = 0; i < 32; i++) {
            bool p = (key[i] >= thr);
            unsigned mask = __ballot_sync(0xFFFFFFFFu, p);
            if (p) {
                int pos = base + __popc(mask & ((1u << lane) - 1u));
                float sv = sc[row][i*32 + lane];
                float e  = expf(sv);
                esum += e;
                if (pos < LISTCAP) {
                    ridx[row*LISTCAP + pos] = i*32 + lane;
                    rw  [row*LISTCAP + pos] = e - 1.0f;
                }
            }
            base += __popc(mask);
        }
        esum += __shfl_xor_sync(0xFFFFFFFFu, esum, 16);
        esum += __shfl_xor_sync(0xFFFFFFFFu, esum, 8);
        esum += __shfl_xor_sync(0xFFFFFFFFu, esum, 4);
        esum += __shfl_xor_sync(0xFFFFFFFFu, esum, 2);
        esum += __shfl_xor_sync(0xFFFFFFFFu, esum, 1);
        __syncwarp();

        const float denom = esum + (float)(SEQ - cnt) + 1e-8f;
        const float dinv  = 1.0f / denom;

        float a0 = g_vsum[bh*DHEAD + lane];
        float a1 = g_vsum[bh*DHEAD + lane + 32];
        const float* vp = g_v + (size_t)bh*SEQ*DHEAD;
        const int m = cnt < LISTCAP ? cnt : LISTCAP;
        for (int j = 0; j < m; j++) {
            float w   = rw[row*LISTCAP + j];
            int   idx = ridx[row*LISTCAP + j];
            const float* vr = vp + (size_t)idx*DHEAD;
            a0 = fmaf(w, vr[lane],      a0);
            a1 = fmaf(w, vr[lane + 32], a1);
        }
        size_t o = ((size_t)b*SEQ + (s0 + row))*DMODEL + h*DHEAD;
        out[o + lane]      = a0 * dinv;
        out[o + lane + 32] = a1 * dinv;
        __syncwarp();
    }
}

// ---------------- launch ----------------
extern "C" void kernel_launch(void* const* d_in, const int* in_sizes, int n_in,
                              void* d_out, int out_size)
{
    const float* Q  = (const float*)d_in[0];
    const float* K  = (const float*)d_in[1];
    const float* V  = (const float*)d_in[2];
    const float* Wq = (const float*)d_in[3];
    const float* bq = (const float*)d_in[4];
    const float* Wk = (const float*)d_in[5];
    const float* bk = (const float*)d_in[6];
    const float* Wv = (const float*)d_in[7];
    const float* bv = (const float*)d_in[8];
    float* out = (float*)d_out;

    float *q, *k;
    cudaGetSymbolAddress((void**)&q, g_q);
    cudaGetSymbolAddress((void**)&k, g_k);

    (void)cudaFuncSetAttribute(attn_kernel,
                               cudaFuncAttributeMaxDynamicSharedMemorySize,
                               ATTN_SMEM_BYTES);

    dim3 gridP(NROWS/128, DMODEL/128, 2);
    proj_kernel<<<gridP, 256>>>(Q, K, Wq, Wk, bq, bk, q, k);

    dim3 gridV(NROWS/128, DMODEL/64);
    vproj_kernel<<<gridV, 256>>>(V, Wv, bv);

    dim3 gridT(BHTOT, SEQ/64);
    ktrans_kernel<<<gridT, 256>>>();

    vsum_kernel<<<BHTOT, 1024>>>();

    dim3 gridA(SEQ/TQ, BHTOT);
    attn_kernel<<<gridA, 256, ATTN_SMEM_BYTES>>>(out);
}